// round 13
// baseline (speedup 1.0000x reference)
#include <cuda_runtime.h>

// db4 dec_lo coefficients
static constexpr float Gf[8] = {
    -0.010597401784997278f,  0.032883011666982945f,
     0.030841381835986965f, -0.18703481171888114f,
    -0.02798376941698385f,   0.6308807679295904f,
     0.7148465705525415f,    0.23037781330885523f };

// Composed analysis+synthesis filters (details zeroed):
//   low[2q]   = sum_{d=-6..7} Ecoef(d) * x_sym[2q+d]
//   low[2q+1] = sum_{d=-6..7} Ocoef(d) * x_sym[2q+d]
__host__ __device__ static constexpr float Ecoef(int d) {
    float r = 0.f;
    for (int j = 0; j < 4; j++) {
        int s = 2 * j + 1 - d;
        if (s >= 0 && s < 8) r += Gf[2 * j + 1] * Gf[s];
    }
    return r;
}
__host__ __device__ static constexpr float Ocoef(int d) {
    float r = 0.f;
    for (int j = 0; j < 4; j++) {
        int s = 2 * j + 1 - d;
        if (s >= 0 && s < 8) r += Gf[2 * j] * Gf[s];
    }
    return r;
}

#define ROW_L  4096
#define ROW_F4 1024

// Each thread computes 8 consecutive outputs (2 float4 groups) from a 24-float
// window loaded as 6 front-batched float4 LDGs (high MLP). CTA covers a
// half-row; grid = rows * 2. No smem, no barriers.
__global__ __launch_bounds__(256) void db4_wide_kernel(
    const float* __restrict__ x,
    float* __restrict__ low,
    float* __restrict__ high)
{
    const int t = threadIdx.x;
    const size_t row = blockIdx.x >> 1;
    const int half = blockIdx.x & 1;
    const float* __restrict__ xr = x + row * (size_t)ROW_L;
    const float4* __restrict__ x4 = (const float4*)xr;

    const int base = half * 2048 + t * 8;   // first output float index
    const int j0 = (base >> 2) - 2;         // first float4 of the 6-float4 window

    // --- front-batched window load: w[c] = x_sym[base + c - 8], c = 0..23 ---
    float w[24];
    if (j0 >= 0 && j0 + 5 < ROW_F4) {       // fast path (all but 2 threads/row)
        float4 v0 = __ldcs(&x4[j0]);
        float4 v1 = __ldcs(&x4[j0 + 1]);
        float4 v2 = __ldcs(&x4[j0 + 2]);
        float4 v3 = __ldcs(&x4[j0 + 3]);
        float4 v4 = __ldcs(&x4[j0 + 4]);
        float4 v5 = __ldcs(&x4[j0 + 5]);
        w[0]=v0.x;  w[1]=v0.y;  w[2]=v0.z;  w[3]=v0.w;
        w[4]=v1.x;  w[5]=v1.y;  w[6]=v1.z;  w[7]=v1.w;
        w[8]=v2.x;  w[9]=v2.y;  w[10]=v2.z; w[11]=v2.w;
        w[12]=v3.x; w[13]=v3.y; w[14]=v3.z; w[15]=v3.w;
        w[16]=v4.x; w[17]=v4.y; w[18]=v4.z; w[19]=v4.w;
        w[20]=v5.x; w[21]=v5.y; w[22]=v5.z; w[23]=v5.w;
    } else {
#pragma unroll
        for (int c = 0; c < 24; c++) {
            int idx = base + c - 8;
            idx = (idx < 0) ? (-1 - idx)
                            : ((idx >= ROW_L) ? (2 * ROW_L - 1 - idx) : idx);
            w[c] = xr[idx];
        }
    }

    constexpr float E[14] = {
        Ecoef(-6), Ecoef(-5), Ecoef(-4), Ecoef(-3), Ecoef(-2), Ecoef(-1),
        Ecoef(0),  Ecoef(1),  Ecoef(2),  Ecoef(3),  Ecoef(4),  Ecoef(5),
        Ecoef(6),  Ecoef(7) };
    constexpr float O[14] = {
        Ocoef(-6), Ocoef(-5), Ocoef(-4), Ocoef(-3), Ocoef(-2), Ocoef(-1),
        Ocoef(0),  Ocoef(1),  Ocoef(2),  Ocoef(3),  Ocoef(4),  Ocoef(5),
        Ocoef(6),  Ocoef(7) };

    // outputs n = base + r:
    //   even r: low = sum_d E[d] * w[d + 2 + r]
    //   odd  r: low = sum_d O[d] * w[d + 2 + (r-1)]
    float lw[8];
#pragma unroll
    for (int p = 0; p < 4; p++) {          // pair p -> r = 2p, 2p+1
        float le = 0.f, lo_ = 0.f;
#pragma unroll
        for (int d = 0; d < 14; d++) {
            const float xv = w[d + 2 + 2 * p];
            le  += E[d] * xv;
            lo_ += O[d] * xv;
        }
        lw[2 * p] = le;
        lw[2 * p + 1] = lo_;
    }

    float* __restrict__ lo = low + row * (size_t)ROW_L;
    float* __restrict__ hi = high + row * (size_t)ROW_L;
    const int i4 = base >> 2;               // output float4 index

    __stcs(&((float4*)lo)[i4],     make_float4(lw[0], lw[1], lw[2], lw[3]));
    __stcs(&((float4*)lo)[i4 + 1], make_float4(lw[4], lw[5], lw[6], lw[7]));
    // x[base + r] = w[r + 8]
    __stcs(&((float4*)hi)[i4],     make_float4(w[8]  - lw[0], w[9]  - lw[1],
                                               w[10] - lw[2], w[11] - lw[3]));
    __stcs(&((float4*)hi)[i4 + 1], make_float4(w[12] - lw[4], w[13] - lw[5],
                                               w[14] - lw[6], w[15] - lw[7]));
}

extern "C" void kernel_launch(void* const* d_in, const int* in_sizes, int n_in,
                              void* d_out, int out_size)
{
    const float* x = (const float*)d_in[0];
    const int n = in_sizes[0];              // B*C*L
    const int rows = n / ROW_L;             // 8192
    float* low = (float*)d_out;             // tuple order: (low_freq, high_freq)
    float* high = (float*)d_out + (size_t)n;

    db4_wide_kernel<<<rows * 2, 256>>>(x, low, high);
}

// round 14
// speedup vs baseline: 1.1920x; 1.1920x over previous
#include <cuda_runtime.h>

// db4 dec_lo coefficients
static constexpr float Gf[8] = {
    -0.010597401784997278f,  0.032883011666982945f,
     0.030841381835986965f, -0.18703481171888114f,
    -0.02798376941698385f,   0.6308807679295904f,
     0.7148465705525415f,    0.23037781330885523f };

// Composed analysis+synthesis filters (details zeroed):
//   low[2q]   = sum_{d=-6..7} Ecoef(d) * x_sym[2q+d]
//   low[2q+1] = sum_{d=-6..7} Ocoef(d) * x_sym[2q+d]
__host__ __device__ static constexpr float Ecoef(int d) {
    float r = 0.f;
    for (int j = 0; j < 4; j++) {
        int s = 2 * j + 1 - d;
        if (s >= 0 && s < 8) r += Gf[2 * j + 1] * Gf[s];
    }
    return r;
}
__host__ __device__ static constexpr float Ocoef(int d) {
    float r = 0.f;
    for (int j = 0; j < 4; j++) {
        int s = 2 * j + 1 - d;
        if (s >= 0 && s < 8) r += Gf[2 * j] * Gf[s];
    }
    return r;
}

#define ROW_L   4096
#define HALF_F  2048          // floats per CTA (half row)
#define HALF_F4 512           // float4 per CTA

// CTA = 128 threads, covers one half-row. sx[m] = x_sym[off + m - 8], m in [0,2064).
__global__ __launch_bounds__(128) void db4_half_kernel(
    const float* __restrict__ x,
    float* __restrict__ low,
    float* __restrict__ high)
{
    __shared__ float sx[HALF_F + 16];   // 2064 floats = 8.3 KB

    const int t = threadIdx.x;
    const size_t row = blockIdx.x >> 1;
    const int half = blockIdx.x & 1;
    const int off = half * HALF_F;      // half-row start (float index in row)
    const float* __restrict__ xr = x + row * (size_t)ROW_L;
    const float4* __restrict__ x4 = (const float4*)xr;

    float4* s4 = (float4*)sx;

    // --- Phase 1: own float4 loads (coalesced) + 16 halo floats ---
    float4 own[4];
    const int f4off = half * HALF_F4;
#pragma unroll
    for (int ii = 0; ii < 4; ii++) {
        own[ii] = __ldcs(&x4[f4off + t + ii * 128]);
    }
    float halo = 0.f;
    if (t < 16) {
        // t in [0,8):   sx[t]        = x_sym[off + t - 8]
        // t in [8,16):  sx[2048 + t] = x_sym[off + 2040 + t]
        int g = (t < 8) ? (off + t - 8) : (off + 2040 + t);
        g = (g < 0) ? (-1 - g) : ((g >= ROW_L) ? (2 * ROW_L - 1 - g) : g);
        halo = __ldcs(&xr[g]);
    }
#pragma unroll
    for (int ii = 0; ii < 4; ii++) {
        s4[t + ii * 128 + 2] = own[ii];   // sx[m], m = 8 .. 2055
    }
    if (t < 16) {
        int dst = (t < 8) ? t : (2048 + t);
        sx[dst] = halo;
    }
    __syncthreads();

    constexpr float E[14] = {
        Ecoef(-6), Ecoef(-5), Ecoef(-4), Ecoef(-3), Ecoef(-2), Ecoef(-1),
        Ecoef(0),  Ecoef(1),  Ecoef(2),  Ecoef(3),  Ecoef(4),  Ecoef(5),
        Ecoef(6),  Ecoef(7) };
    constexpr float O[14] = {
        Ocoef(-6), Ocoef(-5), Ocoef(-4), Ocoef(-3), Ocoef(-2), Ocoef(-1),
        Ocoef(0),  Ocoef(1),  Ocoef(2),  Ocoef(3),  Ocoef(4),  Ocoef(5),
        Ocoef(6),  Ocoef(7) };

    float* __restrict__ lo = low + row * (size_t)ROW_L;
    float* __restrict__ hi = high + row * (size_t)ROW_L;

#pragma unroll
    for (int ii = 0; ii < 4; ii++) {
        const int i = t + ii * 128;        // local float4 index in half-row
        const int i_out = f4off + i;       // global output float4 index

        // window w[c] = sx[4i + c], c = 0..19; own supplies w[8..11] (s4[i+2])
        float w[20];
        float4 v0 = s4[i];
        float4 v1 = s4[i + 1];
        float4 v3 = s4[i + 3];
        float4 v4 = s4[i + 4];
        w[0]=v0.x; w[1]=v0.y; w[2]=v0.z;  w[3]=v0.w;
        w[4]=v1.x; w[5]=v1.y; w[6]=v1.z;  w[7]=v1.w;
        w[8]=own[ii].x; w[9]=own[ii].y; w[10]=own[ii].z; w[11]=own[ii].w;
        w[12]=v3.x; w[13]=v3.y; w[14]=v3.z; w[15]=v3.w;
        w[16]=v4.x; w[17]=v4.y; w[18]=v4.z; w[19]=v4.w;

        float l0 = 0.f, l1 = 0.f, l2 = 0.f, l3 = 0.f;
#pragma unroll
        for (int d = 0; d < 14; d++) {
            l0 += E[d] * w[d + 2];
            l1 += O[d] * w[d + 2];
            l2 += E[d] * w[d + 4];
            l3 += O[d] * w[d + 4];
        }

        __stcs(&((float4*)lo)[i_out], make_float4(l0, l1, l2, l3));
        __stcs(&((float4*)hi)[i_out], make_float4(own[ii].x - l0, own[ii].y - l1,
                                                  own[ii].z - l2, own[ii].w - l3));
    }
}

extern "C" void kernel_launch(void* const* d_in, const int* in_sizes, int n_in,
                              void* d_out, int out_size)
{
    const float* x = (const float*)d_in[0];
    const int n = in_sizes[0];              // B*C*L
    const int rows = n / ROW_L;             // 8192
    float* low = (float*)d_out;             // tuple order: (low_freq, high_freq)
    float* high = (float*)d_out + (size_t)n;

    db4_half_kernel<<<rows * 2, 128>>>(x, low, high);
}